// round 2
// baseline (speedup 1.0000x reference)
#include <cuda_runtime.h>
#include <cuda_bf16.h>
#include <cstdint>

#define NN 100000
#define EE 3200000
#define DD 128
#define BN_EPS 1e-5f

// ---- scratch (device globals: no allocation allowed) ----
__device__ int   g_count[NN];        // degree per node
__device__ int   g_offset[NN];       // CSR row offsets (exclusive prefix of count)
__device__ int   g_fill[NN];         // scatter cursors
__device__ int   g_edge_src[EE];     // src index per edge, grouped by dst
__device__ float g_neigh[(size_t)NN * DD];
__device__ float g_rst[(size_t)NN * DD];
__device__ float g_colsum[DD];
__device__ float g_colsumsq[DD];
__device__ float g_scale[DD];
__device__ float g_shift[DD];

// ---------------------------------------------------------------- zero
__global__ void k_zero() {
    int i = blockIdx.x * blockDim.x + threadIdx.x;
    if (i < NN) { g_count[i] = 0; g_fill[i] = 0; }
    if (i < DD) { g_colsum[i] = 0.f; g_colsumsq[i] = 0.f; }
}

// ---------------------------------------------------------------- degree histogram
__global__ void k_hist(const int* __restrict__ dst) {
    int e = blockIdx.x * blockDim.x + threadIdx.x;
    if (e < EE) atomicAdd(&g_count[dst[e]], 1);
}

// ---------------------------------------------------------------- exclusive scan (1 block)
__global__ void k_scan() {
    const int CH = (NN + 1023) / 1024;   // 98
    __shared__ int ss[1024];
    int t = threadIdx.x;
    int begin = t * CH;
    int end = begin + CH; if (end > NN) end = NN;
    int s = 0;
    for (int i = begin; i < end; i++) s += g_count[i];
    ss[t] = s;
    __syncthreads();
    for (int off = 1; off < 1024; off <<= 1) {
        int v = (t >= off) ? ss[t - off] : 0;
        __syncthreads();
        ss[t] += v;
        __syncthreads();
    }
    int run = (t == 0) ? 0 : ss[t - 1];
    for (int i = begin; i < end; i++) { g_offset[i] = run; run += g_count[i]; }
}

// ---------------------------------------------------------------- scatter into CSR
__global__ void k_scatter(const int* __restrict__ src,
                          const int* __restrict__ dst) {
    int e = blockIdx.x * blockDim.x + threadIdx.x;
    if (e >= EE) return;
    int d = dst[e];
    int p = g_offset[d] + atomicAdd(&g_fill[d], 1);
    g_edge_src[p] = src[e];
}

// ---------------------------------------------------------------- segment mean (1 warp / node)
__global__ void k_aggregate(const float* __restrict__ h) {
    int gwarp = (blockIdx.x * blockDim.x + threadIdx.x) >> 5;
    if (gwarp >= NN) return;
    int lane = threadIdx.x & 31;
    int start = g_offset[gwarp];
    int deg = g_count[gwarp];

    float4 acc = make_float4(0.f, 0.f, 0.f, 0.f);
    int i = 0;
    for (; i + 32 <= deg; i += 32) {
        int s = g_edge_src[start + i + lane];
#pragma unroll
        for (int j = 0; j < 32; j++) {
            int sj = __shfl_sync(0xffffffffu, s, j);
            const float4 v = *(const float4*)(h + (size_t)sj * DD + lane * 4);
            acc.x += v.x; acc.y += v.y; acc.z += v.z; acc.w += v.w;
        }
    }
    {
        int rem = deg - i;
        int s = (lane < rem) ? g_edge_src[start + i + lane] : 0;
        for (int j = 0; j < rem; j++) {
            int sj = __shfl_sync(0xffffffffu, s, j);
            const float4 v = *(const float4*)(h + (size_t)sj * DD + lane * 4);
            acc.x += v.x; acc.y += v.y; acc.z += v.z; acc.w += v.w;
        }
    }
    float inv = 1.0f / fmaxf((float)deg, 1.0f);
    float4 o = make_float4(acc.x * inv, acc.y * inv, acc.z * inv, acc.w * inv);
    *(float4*)(g_neigh + (size_t)gwarp * DD + lane * 4) = o;
}

// ---------------------------------------------------------------- fused GEMM + bias + ReLU
// rst = relu([h | neigh] @ [W_self ; W_neigh] + bias)   (M=NN, N=128, K=256)
__global__ __launch_bounds__(256, 2) void k_gemm(const float* __restrict__ h,
                                                 const float* __restrict__ Ws,
                                                 const float* __restrict__ Wn,
                                                 const float* __restrict__ bias) {
    __shared__ float As[32][128];   // [k][m]
    __shared__ float Bs[32][128];   // [k][n]
    int tid = threadIdx.x;
    int m0 = blockIdx.x * 128;
    int tm = (tid / 16) * 8;
    int tn = (tid % 16) * 8;

    float acc[8][8];
#pragma unroll
    for (int i = 0; i < 8; i++)
#pragma unroll
        for (int j = 0; j < 8; j++) acc[i][j] = 0.f;

    for (int kk = 0; kk < 256; kk += 32) {
        // load A tile (transposed store: global is k-contiguous, smem is [k][m])
#pragma unroll
        for (int l = 0; l < 4; l++) {
            int p = tid + l * 256;         // 0..1023 float4 slots
            int m = p >> 3;                // 0..127
            int k = (p & 7) * 4;           // 0..28
            int gm = m0 + m;
            int gk = kk + k;
            float4 v = make_float4(0.f, 0.f, 0.f, 0.f);
            if (gm < NN) {
                const float* sp = (gk < 128) ? (h + (size_t)gm * DD + gk)
                                             : (g_neigh + (size_t)gm * DD + (gk - 128));
                v = *(const float4*)sp;
            }
            As[k + 0][m] = v.x; As[k + 1][m] = v.y;
            As[k + 2][m] = v.z; As[k + 3][m] = v.w;
        }
        // load B tile (direct copy)
#pragma unroll
        for (int l = 0; l < 4; l++) {
            int p = tid + l * 256;
            int k = p >> 5;                // 0..31
            int n = (p & 31) * 4;          // 0..124
            int gk = kk + k;
            const float* sp = (gk < 128) ? (Ws + (size_t)gk * DD + n)
                                         : (Wn + (size_t)(gk - 128) * DD + n);
            *(float4*)&Bs[k][n] = *(const float4*)sp;
        }
        __syncthreads();
#pragma unroll
        for (int k = 0; k < 32; k++) {
            float a[8], bb[8];
            *(float4*)(a)      = *(float4*)&As[k][tm];
            *(float4*)(a + 4)  = *(float4*)&As[k][tm + 4];
            *(float4*)(bb)     = *(float4*)&Bs[k][tn];
            *(float4*)(bb + 4) = *(float4*)&Bs[k][tn + 4];
#pragma unroll
            for (int i = 0; i < 8; i++)
#pragma unroll
                for (int j = 0; j < 8; j++) acc[i][j] += a[i] * bb[j];
        }
        __syncthreads();
    }

    // epilogue: bias + relu -> g_rst
    float bv[8];
    *(float4*)(bv)     = *(const float4*)(bias + tn);
    *(float4*)(bv + 4) = *(const float4*)(bias + tn + 4);
#pragma unroll
    for (int i = 0; i < 8; i++) {
        int gm = m0 + tm + i;
        if (gm >= NN) continue;
#pragma unroll
        for (int j = 0; j < 8; j += 4) {
            float4 c;
            c.x = fmaxf(acc[i][j + 0] + bv[j + 0], 0.f);
            c.y = fmaxf(acc[i][j + 1] + bv[j + 1], 0.f);
            c.z = fmaxf(acc[i][j + 2] + bv[j + 2], 0.f);
            c.w = fmaxf(acc[i][j + 3] + bv[j + 3], 0.f);
            *(float4*)(g_rst + (size_t)gm * DD + tn + j) = c;
        }
    }
}

// ---------------------------------------------------------------- column stats (sum, sumsq)
__global__ void k_colstats() {
    int j = threadIdx.x;                 // 0..127
    float s = 0.f, sq = 0.f;
    for (int r = blockIdx.x; r < NN; r += gridDim.x) {
        float v = g_rst[(size_t)r * DD + j];
        s += v; sq += v * v;
    }
    atomicAdd(&g_colsum[j], s);
    atomicAdd(&g_colsumsq[j], sq);
}

// ---------------------------------------------------------------- fold BN params
__global__ void k_stats(const float* __restrict__ gamma, const float* __restrict__ beta) {
    int j = threadIdx.x;
    if (j >= DD) return;
    float mean = g_colsum[j] / (float)NN;
    float var = g_colsumsq[j] / (float)NN - mean * mean;
    float rs = rsqrtf(var + BN_EPS);
    float sc = rs * gamma[j];
    g_scale[j] = sc;
    g_shift[j] = beta[j] - mean * sc;
}

// ---------------------------------------------------------------- normalize + residual
__global__ void k_final(const float* __restrict__ h, float* __restrict__ out) {
    int i4 = blockIdx.x * blockDim.x + threadIdx.x;
    const int TOT = NN * DD / 4;
    if (i4 >= TOT) return;
    int c4 = i4 & 31;   // which float4 of the 128 columns
    float4 r = ((const float4*)g_rst)[i4];
    float4 hv = ((const float4*)h)[i4];
    float4 sc = ((const float4*)g_scale)[c4];
    float4 sh = ((const float4*)g_shift)[c4];
    float4 o;
    o.x = hv.x + r.x * sc.x + sh.x;
    o.y = hv.y + r.y * sc.y + sh.y;
    o.z = hv.z + r.z * sc.z + sh.z;
    o.w = hv.w + r.w * sc.w + sh.w;
    ((float4*)out)[i4] = o;
}

// ---------------------------------------------------------------- launch
extern "C" void kernel_launch(void* const* d_in, const int* in_sizes, int n_in,
                              void* d_out, int out_size) {
    const float* h     = (const float*)d_in[0];
    const int*   src   = (const int*)d_in[1];
    const int*   dst   = (const int*)d_in[2];
    const float* Ws    = (const float*)d_in[3];
    const float* Wn    = (const float*)d_in[4];
    const float* bias  = (const float*)d_in[5];
    const float* gamma = (const float*)d_in[6];
    const float* beta  = (const float*)d_in[7];
    float* out = (float*)d_out;

    k_zero<<<(NN + 255) / 256, 256>>>();
    k_hist<<<(EE + 255) / 256, 256>>>(dst);
    k_scan<<<1, 1024>>>();
    k_scatter<<<(EE + 255) / 256, 256>>>(src, dst);
    k_aggregate<<<(NN * 32 + 255) / 256, 256>>>(h);
    k_gemm<<<(NN + 127) / 128, 256>>>(h, Ws, Wn, bias);
    k_colstats<<<256, 128>>>();
    k_stats<<<1, 128>>>(gamma, beta);
    k_final<<<(NN * DD / 4 + 255) / 256, 256>>>(h, out);
}

// round 4
// speedup vs baseline: 1.6329x; 1.6329x over previous
#include <cuda_runtime.h>
#include <cstdint>

#define NN 100000
#define EE 3200000
#define DD 128
#define BN_EPS 1e-5f

// ---- scratch (device globals) ----
__device__ int   g_count[NN];
__device__ int   g_offset[NN];
__device__ int   g_rank[EE];
__device__ int   g_edge_src[EE];
__device__ float g_neigh[(size_t)NN * DD];
__device__ float g_rst[(size_t)NN * DD];
__device__ float g_Wt[128 * 256];    // [n][k], tf32-RN-rounded W^T over [W_self; W_neigh]
__device__ float g_colsum[DD];
__device__ float g_colsumsq[DD];
__device__ float g_scale[DD];
__device__ float g_shift[DD];

// ================= helpers =================
__device__ __forceinline__ uint32_t smem_u32(const void* p) {
    uint32_t a;
    asm("{ .reg .u64 t; cvta.to.shared.u64 t, %1; cvt.u32.u64 %0, t; }" : "=r"(a) : "l"(p));
    return a;
}
__device__ __forceinline__ float tf32_rn(float x) {
    uint32_t y;
    asm("cvt.rna.tf32.f32 %0, %1;" : "=r"(y) : "f"(x));
    return __uint_as_float(y);
}
__device__ __forceinline__ void cp16(uint32_t saddr, const void* gaddr, bool valid) {
    asm volatile("cp.async.cg.shared.global [%0], [%1], 16, %2;"
                 :: "r"(saddr), "l"(gaddr), "r"(valid ? 16u : 0u) : "memory");
}
#define CP_COMMIT() asm volatile("cp.async.commit_group;" ::: "memory")
#define CP_WAIT0()  asm volatile("cp.async.wait_group 0;" ::: "memory")

__device__ __forceinline__ void mma8(float* d, float a0, float a1, float a2, float a3,
                                     float b0, float b1) {
    asm volatile(
        "mma.sync.aligned.m16n8k8.row.col.f32.tf32.tf32.f32 "
        "{%0,%1,%2,%3}, {%4,%5,%6,%7}, {%8,%9}, {%0,%1,%2,%3};"
        : "+f"(d[0]), "+f"(d[1]), "+f"(d[2]), "+f"(d[3])
        : "r"(__float_as_uint(a0)), "r"(__float_as_uint(a1)),
          "r"(__float_as_uint(a2)), "r"(__float_as_uint(a3)),
          "r"(__float_as_uint(b0)), "r"(__float_as_uint(b1)));
}

// ---------------------------------------------------------------- zero
__global__ void k_zero() {
    int i = blockIdx.x * blockDim.x + threadIdx.x;
    if (i < NN) g_count[i] = 0;
    if (i < DD) { g_colsum[i] = 0.f; g_colsumsq[i] = 0.f; }
}

// ---------------------------------------------------------------- W transpose + tf32 round
__global__ void k_wt(const float* __restrict__ Ws, const float* __restrict__ Wn) {
    int i = blockIdx.x * blockDim.x + threadIdx.x;
    if (i >= 128 * 256) return;
    int n = i >> 8, k = i & 255;
    float v = (k < 128) ? Ws[(size_t)k * DD + n] : Wn[(size_t)(k - 128) * DD + n];
    g_Wt[i] = tf32_rn(v);
}

// ---------------------------------------------------------------- degree histogram + edge rank
__global__ void k_hist(const int* __restrict__ dst) {
    int e = blockIdx.x * blockDim.x + threadIdx.x;
    if (e < EE) g_rank[e] = atomicAdd(&g_count[dst[e]], 1);
}

// ---------------------------------------------------------------- exclusive scan (1 block)
__global__ void k_scan() {
    const int CH = (NN + 1023) / 1024;
    __shared__ int ss[1024];
    int t = threadIdx.x;
    int begin = t * CH;
    int end = begin + CH; if (end > NN) end = NN;
    int s = 0;
    for (int i = begin; i < end; i++) s += g_count[i];
    ss[t] = s;
    __syncthreads();
    for (int off = 1; off < 1024; off <<= 1) {
        int v = (t >= off) ? ss[t - off] : 0;
        __syncthreads();
        ss[t] += v;
        __syncthreads();
    }
    int run = (t == 0) ? 0 : ss[t - 1];
    for (int i = begin; i < end; i++) { g_offset[i] = run; run += g_count[i]; }
}

// ---------------------------------------------------------------- scatter into CSR (no atomics)
__global__ void k_scatter(const int* __restrict__ src,
                          const int* __restrict__ dst) {
    int e = blockIdx.x * blockDim.x + threadIdx.x;
    if (e >= EE) return;
    g_edge_src[g_offset[dst[e]] + g_rank[e]] = src[e];
}

// ---------------------------------------------------------------- segment mean (1 warp / node)
__global__ void k_aggregate(const float* __restrict__ h) {
    int gwarp = (blockIdx.x * blockDim.x + threadIdx.x) >> 5;
    if (gwarp >= NN) return;
    int lane = threadIdx.x & 31;
    int start = g_offset[gwarp];
    int deg = g_count[gwarp];

    float4 accA = make_float4(0.f, 0.f, 0.f, 0.f);
    float4 accB = make_float4(0.f, 0.f, 0.f, 0.f);
    int i = 0;
    for (; i + 32 <= deg; i += 32) {
        int s = g_edge_src[start + i + lane];
#pragma unroll
        for (int j = 0; j < 32; j += 2) {
            int s0 = __shfl_sync(0xffffffffu, s, j);
            int s1 = __shfl_sync(0xffffffffu, s, j + 1);
            const float4 v0 = *(const float4*)(h + (size_t)s0 * DD + lane * 4);
            const float4 v1 = *(const float4*)(h + (size_t)s1 * DD + lane * 4);
            accA.x += v0.x; accA.y += v0.y; accA.z += v0.z; accA.w += v0.w;
            accB.x += v1.x; accB.y += v1.y; accB.z += v1.z; accB.w += v1.w;
        }
    }
    {
        int rem = deg - i;
        int s = (lane < rem) ? g_edge_src[start + i + lane] : 0;
        for (int j = 0; j < rem; j++) {
            int sj = __shfl_sync(0xffffffffu, s, j);
            const float4 v = *(const float4*)(h + (size_t)sj * DD + lane * 4);
            accA.x += v.x; accA.y += v.y; accA.z += v.z; accA.w += v.w;
        }
    }
    float inv = 1.0f / fmaxf((float)deg, 1.0f);
    float4 o;
    o.x = (accA.x + accB.x) * inv;
    o.y = (accA.y + accB.y) * inv;
    o.z = (accA.z + accB.z) * inv;
    o.w = (accA.w + accB.w) * inv;
    *(float4*)(g_neigh + (size_t)gwarp * DD + lane * 4) = o;
}

// ---------------------------------------------------------------- TF32 mma.sync GEMM
// rst = relu([h | neigh] @ W + bias); also accumulates BN column sums/sumsq.
// Block: 256 thr (8 warps: 2M x 4N). Tile 128(M) x 128(N), K chunks of 32.
#define STRD 36                       // floats per smem row (32 + 4 pad)
#define TILE (128 * STRD)             // floats per buffer
__global__ __launch_bounds__(256, 2) void k_gemm(const float* __restrict__ h,
                                                 const float* __restrict__ bias) {
    extern __shared__ float sm[];
    float* cs = sm + 4 * TILE;
    float* cq = cs + 128;

    int tid = threadIdx.x;
    int wid = tid >> 5, lane = tid & 31;
    int g = lane >> 2, t = lane & 3;
    int warpM = wid >> 2, warpN = wid & 3;
    int m0 = blockIdx.x * 128;

    if (tid < 128) { cs[tid] = 0.f; cq[tid] = 0.f; }

    uint32_t sb = smem_u32(sm);

    auto issue = [&](int kk, int buf) {
        uint32_t abase = sb + (uint32_t)(buf * TILE) * 4u;
#pragma unroll
        for (int i = 0; i < 4; i++) {
            int slot = tid + i * 256;
            int row = slot >> 3, c4 = slot & 7;
            int gm = m0 + row;
            const float* gp = (kk < 4)
                ? (h + (size_t)gm * DD + kk * 32 + c4 * 4)
                : (g_neigh + (size_t)gm * DD + (kk - 4) * 32 + c4 * 4);
            cp16(abase + row * (STRD * 4) + c4 * 16, gp, gm < NN);
        }
        uint32_t bbase = sb + (uint32_t)((2 + buf) * TILE) * 4u;
#pragma unroll
        for (int i = 0; i < 4; i++) {
            int slot = tid + i * 256;
            int row = slot >> 3, c4 = slot & 7;
            cp16(bbase + row * (STRD * 4) + c4 * 16,
                 g_Wt + (size_t)row * 256 + kk * 32 + c4 * 4, true);
        }
        CP_COMMIT();
    };

    issue(0, 0);

    float acc[4][4][4];
#pragma unroll
    for (int a = 0; a < 4; a++)
#pragma unroll
        for (int b = 0; b < 4; b++)
#pragma unroll
            for (int c = 0; c < 4; c++) acc[a][b][c] = 0.f;

    CP_WAIT0();
    __syncthreads();

    for (int kk = 0; kk < 8; kk++) {
        int buf = kk & 1;
        if (kk < 7) issue(kk + 1, buf ^ 1);
        const float* A = sm + buf * TILE;
        const float* B = sm + (2 + buf) * TILE;
#pragma unroll
        for (int k8 = 0; k8 < 4; k8++) {
            float bf[4][2];
#pragma unroll
            for (int nf = 0; nf < 4; nf++) {
                int n = warpN * 32 + nf * 8 + g;
                bf[nf][0] = B[n * STRD + k8 * 8 + t];
                bf[nf][1] = B[n * STRD + k8 * 8 + t + 4];
            }
#pragma unroll
            for (int mf = 0; mf < 4; mf++) {
                int m = warpM * 64 + mf * 16;
                float a0 = A[(m + g) * STRD + k8 * 8 + t];
                float a1 = A[(m + g + 8) * STRD + k8 * 8 + t];
                float a2 = A[(m + g) * STRD + k8 * 8 + t + 4];
                float a3 = A[(m + g + 8) * STRD + k8 * 8 + t + 4];
#pragma unroll
                for (int nf = 0; nf < 4; nf++)
                    mma8(acc[mf][nf], a0, a1, a2, a3, bf[nf][0], bf[nf][1]);
            }
        }
        CP_WAIT0();
        __syncthreads();
    }

    // ---- epilogue: bias + relu, store, per-block BN partials ----
#pragma unroll
    for (int nf = 0; nf < 4; nf++) {
        int col = warpN * 32 + nf * 8 + 2 * t;
        float2 bv = *(const float2*)(bias + col);
        float s0 = 0.f, s1 = 0.f, q0 = 0.f, q1 = 0.f;
#pragma unroll
        for (int mf = 0; mf < 4; mf++) {
#pragma unroll
            for (int hh = 0; hh < 2; hh++) {
                int row = m0 + warpM * 64 + mf * 16 + g + hh * 8;
                float v0 = fmaxf(acc[mf][nf][hh * 2 + 0] + bv.x, 0.f);
                float v1 = fmaxf(acc[mf][nf][hh * 2 + 1] + bv.y, 0.f);
                if (row < NN) {
                    *(float2*)(g_rst + (size_t)row * DD + col) = make_float2(v0, v1);
                    s0 += v0; q0 += v0 * v0;
                    s1 += v1; q1 += v1 * v1;
                }
            }
        }
        atomicAdd(&cs[col], s0);     atomicAdd(&cs[col + 1], s1);
        atomicAdd(&cq[col], q0);     atomicAdd(&cq[col + 1], q1);
    }
    __syncthreads();
    if (tid < 128) {
        atomicAdd(&g_colsum[tid], cs[tid]);
        atomicAdd(&g_colsumsq[tid], cq[tid]);
    }
}

// ---------------------------------------------------------------- fold BN params
__global__ void k_stats(const float* __restrict__ gamma, const float* __restrict__ beta) {
    int j = threadIdx.x;
    if (j >= DD) return;
    float mean = g_colsum[j] / (float)NN;
    float var = g_colsumsq[j] / (float)NN - mean * mean;
    float rs = rsqrtf(var + BN_EPS);
    float sc = rs * gamma[j];
    g_scale[j] = sc;
    g_shift[j] = beta[j] - mean * sc;
}

// ---------------------------------------------------------------- normalize + residual
__global__ void k_final(const float* __restrict__ h, float* __restrict__ out) {
    int i4 = blockIdx.x * blockDim.x + threadIdx.x;
    const int TOT = NN * DD / 4;
    if (i4 >= TOT) return;
    int c4 = i4 & 31;
    float4 r = ((const float4*)g_rst)[i4];
    float4 hv = ((const float4*)h)[i4];
    float4 sc = ((const float4*)g_scale)[c4];
    float4 sh = ((const float4*)g_shift)[c4];
    float4 o;
    o.x = hv.x + r.x * sc.x + sh.x;
    o.y = hv.y + r.y * sc.y + sh.y;
    o.z = hv.z + r.z * sc.z + sh.z;
    o.w = hv.w + r.w * sc.w + sh.w;
    ((float4*)out)[i4] = o;
}

// ---------------------------------------------------------------- launch
extern "C" void kernel_launch(void* const* d_in, const int* in_sizes, int n_in,
                              void* d_out, int out_size) {
    const float* h     = (const float*)d_in[0];
    const int*   src   = (const int*)d_in[1];
    const int*   dst   = (const int*)d_in[2];
    const float* Ws    = (const float*)d_in[3];
    const float* Wn    = (const float*)d_in[4];
    const float* bias  = (const float*)d_in[5];
    const float* gamma = (const float*)d_in[6];
    const float* beta  = (const float*)d_in[7];
    float* out = (float*)d_out;

    static bool attr_set = false;
    if (!attr_set) {
        cudaFuncSetAttribute(k_gemm, cudaFuncAttributeMaxDynamicSharedMemorySize,
                             (4 * TILE + 256) * 4);
        attr_set = true;
    }

    k_zero<<<(NN + 255) / 256, 256>>>();
    k_wt<<<(128 * 256 + 255) / 256, 256>>>(Ws, Wn);
    k_hist<<<(EE + 255) / 256, 256>>>(dst);
    k_scan<<<1, 1024>>>();
    k_scatter<<<(EE + 255) / 256, 256>>>(src, dst);
    k_aggregate<<<(NN * 32 + 255) / 256, 256>>>(h);
    k_gemm<<<(NN + 127) / 128, 256, (4 * TILE + 256) * 4>>>(h, bias);
    k_stats<<<1, 128>>>(gamma, beta);
    k_final<<<(NN * DD / 4 + 255) / 256, 256>>>(h, out);
}

// round 5
// speedup vs baseline: 2.2135x; 1.3556x over previous
#include <cuda_runtime.h>
#include <cstdint>

#define NN 100000
#define EE 3200000
#define DD 128
#define BN_EPS 1e-5f
#define NBLK 98   // ceil(NN/1024)

// ---- scratch (device globals) ----
__device__ int   g_count[NN];
__device__ int   g_offset[NN];
__device__ int   g_blksum[NBLK];
__device__ int   g_blkoff[NBLK];
__device__ int   g_rank[EE];
__device__ int   g_edge_src[EE];
__device__ float g_neigh[(size_t)NN * DD];
__device__ float g_rst[(size_t)NN * DD];
__device__ float g_Wt[128 * 256];    // [n][k], tf32-RN-rounded W^T over [W_self; W_neigh]
__device__ float g_colsum[DD];
__device__ float g_colsumsq[DD];
__device__ float g_scale[DD];
__device__ float g_shift[DD];

// ================= helpers =================
__device__ __forceinline__ uint32_t smem_u32(const void* p) {
    uint32_t a;
    asm("{ .reg .u64 t; cvta.to.shared.u64 t, %1; cvt.u32.u64 %0, t; }" : "=r"(a) : "l"(p));
    return a;
}
__device__ __forceinline__ float tf32_rn(float x) {
    uint32_t y;
    asm("cvt.rna.tf32.f32 %0, %1;" : "=r"(y) : "f"(x));
    return __uint_as_float(y);
}
__device__ __forceinline__ void cp16(uint32_t saddr, const void* gaddr, bool valid) {
    asm volatile("cp.async.cg.shared.global [%0], [%1], 16, %2;"
                 :: "r"(saddr), "l"(gaddr), "r"(valid ? 16u : 0u) : "memory");
}
#define CP_COMMIT() asm volatile("cp.async.commit_group;" ::: "memory")
#define CP_WAIT0()  asm volatile("cp.async.wait_group 0;" ::: "memory")

__device__ __forceinline__ void mma8(float* d, float a0, float a1, float a2, float a3,
                                     float b0, float b1) {
    asm volatile(
        "mma.sync.aligned.m16n8k8.row.col.f32.tf32.tf32.f32 "
        "{%0,%1,%2,%3}, {%4,%5,%6,%7}, {%8,%9}, {%0,%1,%2,%3};"
        : "+f"(d[0]), "+f"(d[1]), "+f"(d[2]), "+f"(d[3])
        : "r"(__float_as_uint(a0)), "r"(__float_as_uint(a1)),
          "r"(__float_as_uint(a2)), "r"(__float_as_uint(a3)),
          "r"(__float_as_uint(b0)), "r"(__float_as_uint(b1)));
}

// ---------------------------------------------------------------- zero
__global__ void k_zero() {
    int i = blockIdx.x * blockDim.x + threadIdx.x;
    if (i < NN) g_count[i] = 0;
    if (i < DD) { g_colsum[i] = 0.f; g_colsumsq[i] = 0.f; }
}

// ---------------------------------------------------------------- W transpose + tf32 round
__global__ void k_wt(const float* __restrict__ Ws, const float* __restrict__ Wn) {
    int i = blockIdx.x * blockDim.x + threadIdx.x;
    if (i >= 128 * 256) return;
    int n = i >> 8, k = i & 255;
    float v = (k < 128) ? Ws[(size_t)k * DD + n] : Wn[(size_t)(k - 128) * DD + n];
    g_Wt[i] = tf32_rn(v);
}

// ---------------------------------------------------------------- degree histogram + edge rank
__global__ void k_hist(const int* __restrict__ dst) {
    int e = blockIdx.x * blockDim.x + threadIdx.x;
    if (e < EE) g_rank[e] = atomicAdd(&g_count[dst[e]], 1);
}

// ---------------------------------------------------------------- scan phase 1: per-block
__global__ void k_scan_blk() {
    __shared__ int wsum[32];
    int t = threadIdx.x;
    int i = blockIdx.x * 1024 + t;
    int lane = t & 31, wid = t >> 5;
    int v = (i < NN) ? g_count[i] : 0;
    int x = v;
#pragma unroll
    for (int o = 1; o < 32; o <<= 1) {
        int y = __shfl_up_sync(0xffffffffu, x, o);
        if (lane >= o) x += y;
    }
    if (lane == 31) wsum[wid] = x;
    __syncthreads();
    if (wid == 0) {
        int s = wsum[lane];
#pragma unroll
        for (int o = 1; o < 32; o <<= 1) {
            int y = __shfl_up_sync(0xffffffffu, s, o);
            if (lane >= o) s += y;
        }
        wsum[lane] = s;
    }
    __syncthreads();
    int warpoff = (wid == 0) ? 0 : wsum[wid - 1];
    if (i < NN) g_offset[i] = warpoff + x - v;
    if (t == 1023) g_blksum[blockIdx.x] = warpoff + x;
}

// ---------------------------------------------------------------- scan phase 2: block totals
__global__ void k_scan_top() {
    __shared__ int wsum[4];
    int t = threadIdx.x;            // 128 threads
    int lane = t & 31, wid = t >> 5;
    int v = (t < NBLK) ? g_blksum[t] : 0;
    int x = v;
#pragma unroll
    for (int o = 1; o < 32; o <<= 1) {
        int y = __shfl_up_sync(0xffffffffu, x, o);
        if (lane >= o) x += y;
    }
    if (lane == 31) wsum[wid] = x;
    __syncthreads();
    int woff = 0;
    for (int w = 0; w < wid; w++) woff += wsum[w];
    if (t < NBLK) g_blkoff[t] = woff + x - v;
}

// ---------------------------------------------------------------- scan phase 3: add offsets
__global__ void k_scan_add() {
    int i = blockIdx.x * 1024 + threadIdx.x;
    if (i < NN) g_offset[i] += g_blkoff[blockIdx.x];
}

// ---------------------------------------------------------------- scatter into CSR (no atomics)
__global__ void k_scatter(const int* __restrict__ src,
                          const int* __restrict__ dst) {
    int e = blockIdx.x * blockDim.x + threadIdx.x;
    if (e >= EE) return;
    g_edge_src[g_offset[dst[e]] + g_rank[e]] = src[e];
}

// ---------------------------------------------------------------- segment mean (1 warp / node)
__global__ void k_aggregate(const float* __restrict__ h) {
    int gwarp = (blockIdx.x * blockDim.x + threadIdx.x) >> 5;
    if (gwarp >= NN) return;
    int lane = threadIdx.x & 31;
    int start = g_offset[gwarp];
    int deg = g_count[gwarp];

    float4 accA = make_float4(0.f, 0.f, 0.f, 0.f);
    float4 accB = make_float4(0.f, 0.f, 0.f, 0.f);
    int i = 0;
    for (; i + 32 <= deg; i += 32) {
        int s = g_edge_src[start + i + lane];
#pragma unroll
        for (int j = 0; j < 32; j += 2) {
            int s0 = __shfl_sync(0xffffffffu, s, j);
            int s1 = __shfl_sync(0xffffffffu, s, j + 1);
            const float4 v0 = *(const float4*)(h + (size_t)s0 * DD + lane * 4);
            const float4 v1 = *(const float4*)(h + (size_t)s1 * DD + lane * 4);
            accA.x += v0.x; accA.y += v0.y; accA.z += v0.z; accA.w += v0.w;
            accB.x += v1.x; accB.y += v1.y; accB.z += v1.z; accB.w += v1.w;
        }
    }
    {
        int rem = deg - i;
        int s = (lane < rem) ? g_edge_src[start + i + lane] : 0;
        for (int j = 0; j < rem; j++) {
            int sj = __shfl_sync(0xffffffffu, s, j);
            const float4 v = *(const float4*)(h + (size_t)sj * DD + lane * 4);
            accA.x += v.x; accA.y += v.y; accA.z += v.z; accA.w += v.w;
        }
    }
    float inv = 1.0f / fmaxf((float)deg, 1.0f);
    float4 o;
    o.x = (accA.x + accB.x) * inv;
    o.y = (accA.y + accB.y) * inv;
    o.z = (accA.z + accB.z) * inv;
    o.w = (accA.w + accB.w) * inv;
    *(float4*)(g_neigh + (size_t)gwarp * DD + lane * 4) = o;
}

// ---------------------------------------------------------------- TF32 mma.sync GEMM
// rst = relu([h | neigh] @ W + bias); also accumulates BN column sums/sumsq.
#define STRD 36
#define TILE (128 * STRD)
__global__ __launch_bounds__(256, 2) void k_gemm(const float* __restrict__ h,
                                                 const float* __restrict__ bias) {
    extern __shared__ float sm[];
    float* cs = sm + 4 * TILE;
    float* cq = cs + 128;

    int tid = threadIdx.x;
    int wid = tid >> 5, lane = tid & 31;
    int g = lane >> 2, t = lane & 3;
    int warpM = wid >> 2, warpN = wid & 3;
    int m0 = blockIdx.x * 128;

    if (tid < 128) { cs[tid] = 0.f; cq[tid] = 0.f; }

    uint32_t sb = smem_u32(sm);

    auto issue = [&](int kk, int buf) {
        uint32_t abase = sb + (uint32_t)(buf * TILE) * 4u;
#pragma unroll
        for (int i = 0; i < 4; i++) {
            int slot = tid + i * 256;
            int row = slot >> 3, c4 = slot & 7;
            int gm = m0 + row;
            const float* gp = (kk < 4)
                ? (h + (size_t)gm * DD + kk * 32 + c4 * 4)
                : (g_neigh + (size_t)gm * DD + (kk - 4) * 32 + c4 * 4);
            cp16(abase + row * (STRD * 4) + c4 * 16, gp, gm < NN);
        }
        uint32_t bbase = sb + (uint32_t)((2 + buf) * TILE) * 4u;
#pragma unroll
        for (int i = 0; i < 4; i++) {
            int slot = tid + i * 256;
            int row = slot >> 3, c4 = slot & 7;
            cp16(bbase + row * (STRD * 4) + c4 * 16,
                 g_Wt + (size_t)row * 256 + kk * 32 + c4 * 4, true);
        }
        CP_COMMIT();
    };

    issue(0, 0);

    float acc[4][4][4];
#pragma unroll
    for (int a = 0; a < 4; a++)
#pragma unroll
        for (int b = 0; b < 4; b++)
#pragma unroll
            for (int c = 0; c < 4; c++) acc[a][b][c] = 0.f;

    CP_WAIT0();
    __syncthreads();

    for (int kk = 0; kk < 8; kk++) {
        int buf = kk & 1;
        if (kk < 7) issue(kk + 1, buf ^ 1);
        const float* A = sm + buf * TILE;
        const float* B = sm + (2 + buf) * TILE;
#pragma unroll
        for (int k8 = 0; k8 < 4; k8++) {
            float bf[4][2];
#pragma unroll
            for (int nf = 0; nf < 4; nf++) {
                int n = warpN * 32 + nf * 8 + g;
                bf[nf][0] = B[n * STRD + k8 * 8 + t];
                bf[nf][1] = B[n * STRD + k8 * 8 + t + 4];
            }
#pragma unroll
            for (int mf = 0; mf < 4; mf++) {
                int m = warpM * 64 + mf * 16;
                float a0 = A[(m + g) * STRD + k8 * 8 + t];
                float a1 = A[(m + g + 8) * STRD + k8 * 8 + t];
                float a2 = A[(m + g) * STRD + k8 * 8 + t + 4];
                float a3 = A[(m + g + 8) * STRD + k8 * 8 + t + 4];
#pragma unroll
                for (int nf = 0; nf < 4; nf++)
                    mma8(acc[mf][nf], a0, a1, a2, a3, bf[nf][0], bf[nf][1]);
            }
        }
        CP_WAIT0();
        __syncthreads();
    }

    // ---- epilogue: bias + relu, store, per-block BN partials ----
#pragma unroll
    for (int nf = 0; nf < 4; nf++) {
        int col = warpN * 32 + nf * 8 + 2 * t;
        float2 bv = *(const float2*)(bias + col);
        float s0 = 0.f, s1 = 0.f, q0 = 0.f, q1 = 0.f;
#pragma unroll
        for (int mf = 0; mf < 4; mf++) {
#pragma unroll
            for (int hh = 0; hh < 2; hh++) {
                int row = m0 + warpM * 64 + mf * 16 + g + hh * 8;
                float v0 = fmaxf(acc[mf][nf][hh * 2 + 0] + bv.x, 0.f);
                float v1 = fmaxf(acc[mf][nf][hh * 2 + 1] + bv.y, 0.f);
                if (row < NN) {
                    *(float2*)(g_rst + (size_t)row * DD + col) = make_float2(v0, v1);
                    s0 += v0; q0 += v0 * v0;
                    s1 += v1; q1 += v1 * v1;
                }
            }
        }
        atomicAdd(&cs[col], s0);     atomicAdd(&cs[col + 1], s1);
        atomicAdd(&cq[col], q0);     atomicAdd(&cq[col + 1], q1);
    }
    __syncthreads();
    if (tid < 128) {
        atomicAdd(&g_colsum[tid], cs[tid]);
        atomicAdd(&g_colsumsq[tid], cq[tid]);
    }
}

// ---------------------------------------------------------------- fold BN params
__global__ void k_stats(const float* __restrict__ gamma, const float* __restrict__ beta) {
    int j = threadIdx.x;
    if (j >= DD) return;
    float mean = g_colsum[j] / (float)NN;
    float var = g_colsumsq[j] / (float)NN - mean * mean;
    float rs = rsqrtf(var + BN_EPS);
    float sc = rs * gamma[j];
    g_scale[j] = sc;
    g_shift[j] = beta[j] - mean * sc;
}

// ---------------------------------------------------------------- normalize + residual
__global__ void k_final(const float* __restrict__ h, float* __restrict__ out) {
    int i4 = blockIdx.x * blockDim.x + threadIdx.x;
    const int TOT = NN * DD / 4;
    if (i4 >= TOT) return;
    int c4 = i4 & 31;
    float4 r = ((const float4*)g_rst)[i4];
    float4 hv = ((const float4*)h)[i4];
    float4 sc = ((const float4*)g_scale)[c4];
    float4 sh = ((const float4*)g_shift)[c4];
    float4 o;
    o.x = hv.x + r.x * sc.x + sh.x;
    o.y = hv.y + r.y * sc.y + sh.y;
    o.z = hv.z + r.z * sc.z + sh.z;
    o.w = hv.w + r.w * sc.w + sh.w;
    ((float4*)out)[i4] = o;
}

// ---------------------------------------------------------------- launch
extern "C" void kernel_launch(void* const* d_in, const int* in_sizes, int n_in,
                              void* d_out, int out_size) {
    const float* h     = (const float*)d_in[0];
    const int*   src   = (const int*)d_in[1];
    const int*   dst   = (const int*)d_in[2];
    const float* Ws    = (const float*)d_in[3];
    const float* Wn    = (const float*)d_in[4];
    const float* bias  = (const float*)d_in[5];
    const float* gamma = (const float*)d_in[6];
    const float* beta  = (const float*)d_in[7];
    float* out = (float*)d_out;

    static bool attr_set = false;
    if (!attr_set) {
        cudaFuncSetAttribute(k_gemm, cudaFuncAttributeMaxDynamicSharedMemorySize,
                             (4 * TILE + 256) * 4);
        attr_set = true;
    }

    k_zero<<<(NN + 255) / 256, 256>>>();
    k_wt<<<(128 * 256 + 255) / 256, 256>>>(Ws, Wn);
    k_hist<<<(EE + 255) / 256, 256>>>(dst);
    k_scan_blk<<<NBLK, 1024>>>();
    k_scan_top<<<1, 128>>>();
    k_scan_add<<<NBLK, 1024>>>();
    k_scatter<<<(EE + 255) / 256, 256>>>(src, dst);
    k_aggregate<<<(NN * 32 + 255) / 256, 256>>>(h);
    k_gemm<<<(NN + 127) / 128, 256, (4 * TILE + 256) * 4>>>(h, bias);
    k_stats<<<1, 128>>>(gamma, beta);
    k_final<<<(NN * DD / 4 + 255) / 256, 256>>>(h, out);
}

// round 8
// speedup vs baseline: 2.4319x; 1.0987x over previous
#include <cuda_runtime.h>
#include <cuda_fp16.h>
#include <cstdint>

#define NN 100000
#define EE 3200000
#define DD 128
#define BN_EPS 1e-5f
#define NBLK 98   // ceil(NN/1024)

// ---- scratch (device globals) ----
__device__ int    g_count[NN];
__device__ int    g_offset[NN];
__device__ int    g_blksum[NBLK];
__device__ int    g_blkoff[NBLK];
__device__ int    g_rank[EE];
__device__ int    g_edge_src[EE];
__device__ __half g_h16[(size_t)NN * DD];
__device__ float  g_neigh[(size_t)NN * DD];
__device__ float  g_rst[(size_t)NN * DD];
__device__ float  g_Wt[128 * 256];    // [n][k], tf32-RN-rounded W^T
__device__ float  g_colsum[DD];
__device__ float  g_colsumsq[DD];
__device__ float  g_scale[DD];
__device__ float  g_shift[DD];

// ================= helpers =================
__device__ __forceinline__ uint32_t smem_u32(const void* p) {
    uint32_t a;
    asm("{ .reg .u64 t; cvta.to.shared.u64 t, %1; cvt.u32.u64 %0, t; }" : "=r"(a) : "l"(p));
    return a;
}
__device__ __forceinline__ float tf32_rn(float x) {
    uint32_t y;
    asm("cvt.rna.tf32.f32 %0, %1;" : "=r"(y) : "f"(x));
    return __uint_as_float(y);
}
__device__ __forceinline__ void cp16(uint32_t saddr, const void* gaddr, bool valid) {
    asm volatile("cp.async.cg.shared.global [%0], [%1], 16, %2;"
                 :: "r"(saddr), "l"(gaddr), "r"(valid ? 16u : 0u) : "memory");
}
#define CP_COMMIT() asm volatile("cp.async.commit_group;" ::: "memory")
#define CP_WAIT0()  asm volatile("cp.async.wait_group 0;" ::: "memory")

__device__ __forceinline__ void mma8(float* d, float a0, float a1, float a2, float a3,
                                     float b0, float b1) {
    asm volatile(
        "mma.sync.aligned.m16n8k8.row.col.f32.tf32.tf32.f32 "
        "{%0,%1,%2,%3}, {%4,%5,%6,%7}, {%8,%9}, {%0,%1,%2,%3};"
        : "+f"(d[0]), "+f"(d[1]), "+f"(d[2]), "+f"(d[3])
        : "r"(__float_as_uint(a0)), "r"(__float_as_uint(a1)),
          "r"(__float_as_uint(a2)), "r"(__float_as_uint(a3)),
          "r"(__float_as_uint(b0)), "r"(__float_as_uint(b1)));
}

// ---------------------------------------------------------------- zero
__global__ void k_zero() {
    int i = blockIdx.x * blockDim.x + threadIdx.x;
    if (i < NN) g_count[i] = 0;
    if (i < DD) { g_colsum[i] = 0.f; g_colsumsq[i] = 0.f; }
}

// ---------------------------------------------------------------- h -> fp16 copy
__global__ void k_h16(const float* __restrict__ h) {
    int i = blockIdx.x * blockDim.x + threadIdx.x;   // one per 8 floats
    const int TOT = NN * DD / 8;
    if (i >= TOT) return;
    float4 a = ((const float4*)h)[2 * i];
    float4 b = ((const float4*)h)[2 * i + 1];
    __half2 r[4];
    r[0] = __float22half2_rn(make_float2(a.x, a.y));
    r[1] = __float22half2_rn(make_float2(a.z, a.w));
    r[2] = __float22half2_rn(make_float2(b.x, b.y));
    r[3] = __float22half2_rn(make_float2(b.z, b.w));
    ((uint4*)g_h16)[i] = *(uint4*)r;
}

// ---------------------------------------------------------------- W transpose + tf32 round
__global__ void k_wt(const float* __restrict__ Ws, const float* __restrict__ Wn) {
    int i = blockIdx.x * blockDim.x + threadIdx.x;
    if (i >= 128 * 256) return;
    int n = i >> 8, k = i & 255;
    float v = (k < 128) ? Ws[(size_t)k * DD + n] : Wn[(size_t)(k - 128) * DD + n];
    g_Wt[i] = tf32_rn(v);
}

// ---------------------------------------------------------------- degree histogram + edge rank
__global__ void k_hist(const int* __restrict__ dst) {
    int e = blockIdx.x * blockDim.x + threadIdx.x;
    if (e < EE) g_rank[e] = atomicAdd(&g_count[dst[e]], 1);
}

// ---------------------------------------------------------------- scan phase 1: per-block
__global__ void k_scan_blk() {
    __shared__ int wsum[32];
    int t = threadIdx.x;
    int i = blockIdx.x * 1024 + t;
    int lane = t & 31, wid = t >> 5;
    int v = (i < NN) ? g_count[i] : 0;
    int x = v;
#pragma unroll
    for (int o = 1; o < 32; o <<= 1) {
        int y = __shfl_up_sync(0xffffffffu, x, o);
        if (lane >= o) x += y;
    }
    if (lane == 31) wsum[wid] = x;
    __syncthreads();
    if (wid == 0) {
        int s = wsum[lane];
#pragma unroll
        for (int o = 1; o < 32; o <<= 1) {
            int y = __shfl_up_sync(0xffffffffu, s, o);
            if (lane >= o) s += y;
        }
        wsum[lane] = s;
    }
    __syncthreads();
    int warpoff = (wid == 0) ? 0 : wsum[wid - 1];
    if (i < NN) g_offset[i] = warpoff + x - v;
    if (t == 1023) g_blksum[blockIdx.x] = warpoff + x;
}

// ---------------------------------------------------------------- scan phase 2: block totals
__global__ void k_scan_top() {
    __shared__ int wsum[4];
    int t = threadIdx.x;            // 128 threads
    int lane = t & 31, wid = t >> 5;
    int v = (t < NBLK) ? g_blksum[t] : 0;
    int x = v;
#pragma unroll
    for (int o = 1; o < 32; o <<= 1) {
        int y = __shfl_up_sync(0xffffffffu, x, o);
        if (lane >= o) x += y;
    }
    if (lane == 31) wsum[wid] = x;
    __syncthreads();
    int woff = 0;
    for (int w = 0; w < wid; w++) woff += wsum[w];
    if (t < NBLK) g_blkoff[t] = woff + x - v;
}

// ---------------------------------------------------------------- scan phase 3: add offsets
__global__ void k_scan_add() {
    int i = blockIdx.x * 1024 + threadIdx.x;
    if (i < NN) g_offset[i] += g_blkoff[blockIdx.x];
}

// ---------------------------------------------------------------- scatter into CSR (no atomics)
__global__ void k_scatter(const int* __restrict__ src,
                          const int* __restrict__ dst) {
    int e = blockIdx.x * blockDim.x + threadIdx.x;
    if (e >= EE) return;
    g_edge_src[g_offset[dst[e]] + g_rank[e]] = src[e];
}

// ---------------------------------------------------------------- segment mean (1 warp / node, fp16 gather)
// Each lane owns 4 columns: one uint2 (4 halves) per edge row.
__global__ void k_aggregate() {
    int gwarp = (blockIdx.x * blockDim.x + threadIdx.x) >> 5;
    if (gwarp >= NN) return;
    int lane = threadIdx.x & 31;
    int start = g_offset[gwarp];
    int deg = g_count[gwarp];

    float accA[4] = {0, 0, 0, 0};
    float accB[4] = {0, 0, 0, 0};

    int i = 0;
    for (; i + 32 <= deg; i += 32) {
        int s = g_edge_src[start + i + lane];
#pragma unroll
        for (int j = 0; j < 32; j += 2) {
            int s0 = __shfl_sync(0xffffffffu, s, j);
            int s1 = __shfl_sync(0xffffffffu, s, j + 1);
            uint2 u0 = *((const uint2*)(g_h16 + (size_t)s0 * DD) + lane);
            uint2 u1 = *((const uint2*)(g_h16 + (size_t)s1 * DD) + lane);
            {
                float2 f0 = __half22float2(*(__half2*)&u0.x);
                float2 f1 = __half22float2(*(__half2*)&u0.y);
                accA[0] += f0.x; accA[1] += f0.y; accA[2] += f1.x; accA[3] += f1.y;
            }
            {
                float2 f0 = __half22float2(*(__half2*)&u1.x);
                float2 f1 = __half22float2(*(__half2*)&u1.y);
                accB[0] += f0.x; accB[1] += f0.y; accB[2] += f1.x; accB[3] += f1.y;
            }
        }
    }
    {
        int rem = deg - i;
        int s = (lane < rem) ? g_edge_src[start + i + lane] : 0;
        for (int j = 0; j < rem; j++) {
            int sj = __shfl_sync(0xffffffffu, s, j);
            uint2 u = *((const uint2*)(g_h16 + (size_t)sj * DD) + lane);
            float2 f0 = __half22float2(*(__half2*)&u.x);
            float2 f1 = __half22float2(*(__half2*)&u.y);
            accA[0] += f0.x; accA[1] += f0.y; accA[2] += f1.x; accA[3] += f1.y;
        }
    }
    float inv = 1.0f / fmaxf((float)deg, 1.0f);
    float4 o;
    o.x = (accA[0] + accB[0]) * inv;
    o.y = (accA[1] + accB[1]) * inv;
    o.z = (accA[2] + accB[2]) * inv;
    o.w = (accA[3] + accB[3]) * inv;
    *(float4*)(g_neigh + (size_t)gwarp * DD + lane * 4) = o;
}

// ---------------------------------------------------------------- TF32 mma.sync GEMM
// rst = relu([h | neigh] @ W + bias); also accumulates BN column sums/sumsq.
#define STRD 36
#define TILE (128 * STRD)
__global__ __launch_bounds__(256, 2) void k_gemm(const float* __restrict__ h,
                                                 const float* __restrict__ bias) {
    extern __shared__ float sm[];
    float* cs = sm + 4 * TILE;
    float* cq = cs + 128;

    int tid = threadIdx.x;
    int wid = tid >> 5, lane = tid & 31;
    int g = lane >> 2, t = lane & 3;
    int warpM = wid >> 2, warpN = wid & 3;
    int m0 = blockIdx.x * 128;

    if (tid < 128) { cs[tid] = 0.f; cq[tid] = 0.f; }

    uint32_t sb = smem_u32(sm);

    auto issue = [&](int kk, int buf) {
        uint32_t abase = sb + (uint32_t)(buf * TILE) * 4u;
#pragma unroll
        for (int i = 0; i < 4; i++) {
            int slot = tid + i * 256;
            int row = slot >> 3, c4 = slot & 7;
            int gm = m0 + row;
            const float* gp = (kk < 4)
                ? (h + (size_t)gm * DD + kk * 32 + c4 * 4)
                : (g_neigh + (size_t)gm * DD + (kk - 4) * 32 + c4 * 4);
            cp16(abase + row * (STRD * 4) + c4 * 16, gp, gm < NN);
        }
        uint32_t bbase = sb + (uint32_t)((2 + buf) * TILE) * 4u;
#pragma unroll
        for (int i = 0; i < 4; i++) {
            int slot = tid + i * 256;
            int row = slot >> 3, c4 = slot & 7;
            cp16(bbase + row * (STRD * 4) + c4 * 16,
                 g_Wt + (size_t)row * 256 + kk * 32 + c4 * 4, true);
        }
        CP_COMMIT();
    };

    issue(0, 0);

    float acc[4][4][4];
#pragma unroll
    for (int a = 0; a < 4; a++)
#pragma unroll
        for (int b = 0; b < 4; b++)
#pragma unroll
            for (int c = 0; c < 4; c++) acc[a][b][c] = 0.f;

    CP_WAIT0();
    __syncthreads();

    for (int kk = 0; kk < 8; kk++) {
        int buf = kk & 1;
        if (kk < 7) issue(kk + 1, buf ^ 1);
        const float* A = sm + buf * TILE;
        const float* B = sm + (2 + buf) * TILE;
#pragma unroll
        for (int k8 = 0; k8 < 4; k8++) {
            float bf[4][2];
#pragma unroll
            for (int nf = 0; nf < 4; nf++) {
                int n = warpN * 32 + nf * 8 + g;
                bf[nf][0] = B[n * STRD + k8 * 8 + t];
                bf[nf][1] = B[n * STRD + k8 * 8 + t + 4];
            }
#pragma unroll
            for (int mf = 0; mf < 4; mf++) {
                int m = warpM * 64 + mf * 16;
                float a0 = A[(m + g) * STRD + k8 * 8 + t];
                float a1 = A[(m + g + 8) * STRD + k8 * 8 + t];
                float a2 = A[(m + g) * STRD + k8 * 8 + t + 4];
                float a3 = A[(m + g + 8) * STRD + k8 * 8 + t + 4];
#pragma unroll
                for (int nf = 0; nf < 4; nf++)
                    mma8(acc[mf][nf], a0, a1, a2, a3, bf[nf][0], bf[nf][1]);
            }
        }
        CP_WAIT0();
        __syncthreads();
    }

    // ---- epilogue: bias + relu, store, per-block BN partials ----
#pragma unroll
    for (int nf = 0; nf < 4; nf++) {
        int col = warpN * 32 + nf * 8 + 2 * t;
        float2 bv = *(const float2*)(bias + col);
        float s0 = 0.f, s1 = 0.f, q0 = 0.f, q1 = 0.f;
#pragma unroll
        for (int mf = 0; mf < 4; mf++) {
#pragma unroll
            for (int hh = 0; hh < 2; hh++) {
                int row = m0 + warpM * 64 + mf * 16 + g + hh * 8;
                float v0 = fmaxf(acc[mf][nf][hh * 2 + 0] + bv.x, 0.f);
                float v1 = fmaxf(acc[mf][nf][hh * 2 + 1] + bv.y, 0.f);
                if (row < NN) {
                    *(float2*)(g_rst + (size_t)row * DD + col) = make_float2(v0, v1);
                    s0 += v0; q0 += v0 * v0;
                    s1 += v1; q1 += v1 * v1;
                }
            }
        }
        atomicAdd(&cs[col], s0);     atomicAdd(&cs[col + 1], s1);
        atomicAdd(&cq[col], q0);     atomicAdd(&cq[col + 1], q1);
    }
    __syncthreads();
    if (tid < 128) {
        atomicAdd(&g_colsum[tid], cs[tid]);
        atomicAdd(&g_colsumsq[tid], cq[tid]);
    }
}

// ---------------------------------------------------------------- fold BN params
__global__ void k_stats(const float* __restrict__ gamma, const float* __restrict__ beta) {
    int j = threadIdx.x;
    if (j >= DD) return;
    float mean = g_colsum[j] / (float)NN;
    float var = g_colsumsq[j] / (float)NN - mean * mean;
    float rs = rsqrtf(var + BN_EPS);
    float sc = rs * gamma[j];
    g_scale[j] = sc;
    g_shift[j] = beta[j] - mean * sc;
}

// ---------------------------------------------------------------- normalize + residual
__global__ void k_final(const float* __restrict__ h, float* __restrict__ out) {
    int i4 = blockIdx.x * blockDim.x + threadIdx.x;
    const int TOT = NN * DD / 4;
    if (i4 >= TOT) return;
    int c4 = i4 & 31;
    float4 r = ((const float4*)g_rst)[i4];
    float4 hv = ((const float4*)h)[i4];
    float4 sc = ((const float4*)g_scale)[c4];
    float4 sh = ((const float4*)g_shift)[c4];
    float4 o;
    o.x = hv.x + r.x * sc.x + sh.x;
    o.y = hv.y + r.y * sc.y + sh.y;
    o.z = hv.z + r.z * sc.z + sh.z;
    o.w = hv.w + r.w * sc.w + sh.w;
    ((float4*)out)[i4] = o;
}

// ---------------------------------------------------------------- launch
extern "C" void kernel_launch(void* const* d_in, const int* in_sizes, int n_in,
                              void* d_out, int out_size) {
    const float* h     = (const float*)d_in[0];
    const int*   src   = (const int*)d_in[1];
    const int*   dst   = (const int*)d_in[2];
    const float* Ws    = (const float*)d_in[3];
    const float* Wn    = (const float*)d_in[4];
    const float* bias  = (const float*)d_in[5];
    const float* gamma = (const float*)d_in[6];
    const float* beta  = (const float*)d_in[7];
    float* out = (float*)d_out;

    static bool attr_set = false;
    if (!attr_set) {
        cudaFuncSetAttribute(k_gemm, cudaFuncAttributeMaxDynamicSharedMemorySize,
                             (4 * TILE + 256) * 4);
        attr_set = true;
    }

    k_zero<<<(NN + 255) / 256, 256>>>();
    k_h16<<<(NN * DD / 8 + 255) / 256, 256>>>(h);
    k_wt<<<(128 * 256 + 255) / 256, 256>>>(Ws, Wn);
    k_hist<<<(EE + 255) / 256, 256>>>(dst);
    k_scan_blk<<<NBLK, 1024>>>();
    k_scan_top<<<1, 128>>>();
    k_scan_add<<<NBLK, 1024>>>();
    k_scatter<<<(EE + 255) / 256, 256>>>(src, dst);
    k_aggregate<<<(NN * 32 + 255) / 256, 256>>>();
    k_gemm<<<(NN + 127) / 128, 256, (4 * TILE + 256) * 4>>>(h, bias);
    k_stats<<<1, 128>>>(gamma, beta);
    k_final<<<(NN * DD / 4 + 255) / 256, 256>>>(h, out);
}

// round 9
// speedup vs baseline: 2.6333x; 1.0828x over previous
#include <cuda_runtime.h>
#include <cuda_fp16.h>
#include <cstdint>

#define NN 100000
#define EE 3200000
#define DD 128
#define BN_EPS 1e-5f
#define NBLK 98   // ceil(NN/1024)

// ---- scratch (device globals) ----
__device__ int    g_count[NN];
__device__ int    g_offset[NN];
__device__ int    g_blksum[NBLK];
__device__ int    g_blkoff[NBLK];
__device__ int    g_rank[EE];
__device__ int    g_edge_src[EE];
__device__ __half g_h16[(size_t)NN * DD];
__device__ __half g_neigh16[(size_t)NN * DD];
__device__ __half g_rst16[(size_t)NN * DD];
__device__ __half g_Wt16[128 * 256];   // [n][k] fp16 W^T over [W_self; W_neigh]
__device__ float  g_colsum[DD];
__device__ float  g_colsumsq[DD];
__device__ float  g_scale[DD];
__device__ float  g_shift[DD];

// ================= helpers =================
__device__ __forceinline__ uint32_t smem_u32(const void* p) {
    uint32_t a;
    asm("{ .reg .u64 t; cvta.to.shared.u64 t, %1; cvt.u32.u64 %0, t; }" : "=r"(a) : "l"(p));
    return a;
}
__device__ __forceinline__ void cp16(uint32_t saddr, const void* gaddr, bool valid) {
    asm volatile("cp.async.cg.shared.global [%0], [%1], 16, %2;"
                 :: "r"(saddr), "l"(gaddr), "r"(valid ? 16u : 0u) : "memory");
}
#define CP_COMMIT() asm volatile("cp.async.commit_group;" ::: "memory")
#define CP_WAIT0()  asm volatile("cp.async.wait_group 0;" ::: "memory")

__device__ __forceinline__ void mma16(float* d, uint32_t a0, uint32_t a1, uint32_t a2,
                                      uint32_t a3, uint32_t b0, uint32_t b1) {
    asm volatile(
        "mma.sync.aligned.m16n8k16.row.col.f32.f16.f16.f32 "
        "{%0,%1,%2,%3}, {%4,%5,%6,%7}, {%8,%9}, {%0,%1,%2,%3};"
        : "+f"(d[0]), "+f"(d[1]), "+f"(d[2]), "+f"(d[3])
        : "r"(a0), "r"(a1), "r"(a2), "r"(a3), "r"(b0), "r"(b1));
}

// ---------------------------------------------------------------- zero
__global__ void k_zero() {
    int i = blockIdx.x * blockDim.x + threadIdx.x;
    if (i < NN) g_count[i] = 0;
    if (i < DD) { g_colsum[i] = 0.f; g_colsumsq[i] = 0.f; }
}

// ---------------------------------------------------------------- h -> fp16 copy
__global__ void k_h16(const float* __restrict__ h) {
    int i = blockIdx.x * blockDim.x + threadIdx.x;   // one per 8 floats
    const int TOT = NN * DD / 8;
    if (i >= TOT) return;
    float4 a = ((const float4*)h)[2 * i];
    float4 b = ((const float4*)h)[2 * i + 1];
    __half2 r[4];
    r[0] = __float22half2_rn(make_float2(a.x, a.y));
    r[1] = __float22half2_rn(make_float2(a.z, a.w));
    r[2] = __float22half2_rn(make_float2(b.x, b.y));
    r[3] = __float22half2_rn(make_float2(b.z, b.w));
    ((uint4*)g_h16)[i] = *(uint4*)r;
}

// ---------------------------------------------------------------- W transpose + fp16 round
__global__ void k_wt(const float* __restrict__ Ws, const float* __restrict__ Wn) {
    int i = blockIdx.x * blockDim.x + threadIdx.x;
    if (i >= 128 * 256) return;
    int n = i >> 8, k = i & 255;
    float v = (k < 128) ? Ws[(size_t)k * DD + n] : Wn[(size_t)(k - 128) * DD + n];
    g_Wt16[i] = __float2half_rn(v);
}

// ---------------------------------------------------------------- degree histogram + edge rank (4-wide)
__global__ void k_hist(const int* __restrict__ dst) {
    int e4 = blockIdx.x * blockDim.x + threadIdx.x;
    if (e4 >= EE / 4) return;
    int4 d = ((const int4*)dst)[e4];
    int4 r;
    r.x = atomicAdd(&g_count[d.x], 1);
    r.y = atomicAdd(&g_count[d.y], 1);
    r.z = atomicAdd(&g_count[d.z], 1);
    r.w = atomicAdd(&g_count[d.w], 1);
    ((int4*)g_rank)[e4] = r;
}

// ---------------------------------------------------------------- scan phase 1: per-block
__global__ void k_scan_blk() {
    __shared__ int wsum[32];
    int t = threadIdx.x;
    int i = blockIdx.x * 1024 + t;
    int lane = t & 31, wid = t >> 5;
    int v = (i < NN) ? g_count[i] : 0;
    int x = v;
#pragma unroll
    for (int o = 1; o < 32; o <<= 1) {
        int y = __shfl_up_sync(0xffffffffu, x, o);
        if (lane >= o) x += y;
    }
    if (lane == 31) wsum[wid] = x;
    __syncthreads();
    if (wid == 0) {
        int s = wsum[lane];
#pragma unroll
        for (int o = 1; o < 32; o <<= 1) {
            int y = __shfl_up_sync(0xffffffffu, s, o);
            if (lane >= o) s += y;
        }
        wsum[lane] = s;
    }
    __syncthreads();
    int warpoff = (wid == 0) ? 0 : wsum[wid - 1];
    if (i < NN) g_offset[i] = warpoff + x - v;
    if (t == 1023) g_blksum[blockIdx.x] = warpoff + x;
}

// ---------------------------------------------------------------- scan phase 2: block totals
__global__ void k_scan_top() {
    __shared__ int wsum[4];
    int t = threadIdx.x;            // 128 threads
    int lane = t & 31, wid = t >> 5;
    int v = (t < NBLK) ? g_blksum[t] : 0;
    int x = v;
#pragma unroll
    for (int o = 1; o < 32; o <<= 1) {
        int y = __shfl_up_sync(0xffffffffu, x, o);
        if (lane >= o) x += y;
    }
    if (lane == 31) wsum[wid] = x;
    __syncthreads();
    int woff = 0;
    for (int w = 0; w < wid; w++) woff += wsum[w];
    if (t < NBLK) g_blkoff[t] = woff + x - v;
}

// ---------------------------------------------------------------- scan phase 3: add offsets
__global__ void k_scan_add() {
    int i = blockIdx.x * 1024 + threadIdx.x;
    if (i < NN) g_offset[i] += g_blkoff[blockIdx.x];
}

// ---------------------------------------------------------------- scatter into CSR (no atomics, 4-wide)
__global__ void k_scatter(const int* __restrict__ src,
                          const int* __restrict__ dst) {
    int e4 = blockIdx.x * blockDim.x + threadIdx.x;
    if (e4 >= EE / 4) return;
    int4 d = ((const int4*)dst)[e4];
    int4 s = ((const int4*)src)[e4];
    int4 r = ((const int4*)g_rank)[e4];
    g_edge_src[g_offset[d.x] + r.x] = s.x;
    g_edge_src[g_offset[d.y] + r.y] = s.y;
    g_edge_src[g_offset[d.z] + r.z] = s.z;
    g_edge_src[g_offset[d.w] + r.w] = s.w;
}

// ---------------------------------------------------------------- segment mean (1 warp / node, fp16 gather)
// Each lane owns 4 columns: one uint2 (4 halves) per edge row. Output fp16.
__global__ void k_aggregate() {
    int gwarp = (blockIdx.x * blockDim.x + threadIdx.x) >> 5;
    if (gwarp >= NN) return;
    int lane = threadIdx.x & 31;
    int start = g_offset[gwarp];
    int deg = g_count[gwarp];

    float accA[4] = {0, 0, 0, 0};
    float accB[4] = {0, 0, 0, 0};

    int i = 0;
    for (; i + 32 <= deg; i += 32) {
        int s = g_edge_src[start + i + lane];
#pragma unroll
        for (int j = 0; j < 32; j += 2) {
            int s0 = __shfl_sync(0xffffffffu, s, j);
            int s1 = __shfl_sync(0xffffffffu, s, j + 1);
            uint2 u0 = *((const uint2*)(g_h16 + (size_t)s0 * DD) + lane);
            uint2 u1 = *((const uint2*)(g_h16 + (size_t)s1 * DD) + lane);
            {
                float2 f0 = __half22float2(*(__half2*)&u0.x);
                float2 f1 = __half22float2(*(__half2*)&u0.y);
                accA[0] += f0.x; accA[1] += f0.y; accA[2] += f1.x; accA[3] += f1.y;
            }
            {
                float2 f0 = __half22float2(*(__half2*)&u1.x);
                float2 f1 = __half22float2(*(__half2*)&u1.y);
                accB[0] += f0.x; accB[1] += f0.y; accB[2] += f1.x; accB[3] += f1.y;
            }
        }
    }
    {
        int rem = deg - i;
        int s = (lane < rem) ? g_edge_src[start + i + lane] : 0;
        for (int j = 0; j < rem; j++) {
            int sj = __shfl_sync(0xffffffffu, s, j);
            uint2 u = *((const uint2*)(g_h16 + (size_t)sj * DD) + lane);
            float2 f0 = __half22float2(*(__half2*)&u.x);
            float2 f1 = __half22float2(*(__half2*)&u.y);
            accA[0] += f0.x; accA[1] += f0.y; accA[2] += f1.x; accA[3] += f1.y;
        }
    }
    float inv = 1.0f / fmaxf((float)deg, 1.0f);
    __half2 p0 = __float22half2_rn(make_float2((accA[0] + accB[0]) * inv,
                                               (accA[1] + accB[1]) * inv));
    __half2 p1 = __float22half2_rn(make_float2((accA[2] + accB[2]) * inv,
                                               (accA[3] + accB[3]) * inv));
    uint2 o;
    o.x = *(uint32_t*)&p0;
    o.y = *(uint32_t*)&p1;
    *((uint2*)(g_neigh16 + (size_t)gwarp * DD) + lane) = o;
}

// ---------------------------------------------------------------- FP16 mma.sync GEMM
// rst = relu([h | neigh] @ W + bias); BN column sums fused (fp32 exact).
// Block 256 thr (8 warps: 2M x 4N). Tile 128(M) x 128(N), K chunks of 32 (2 k16 steps).
#define STRD16 40                     // halves per smem row (32 + 8 pad = 80B, 16B aligned)
#define TILE16 (128 * STRD16)         // halves per buffer
__global__ __launch_bounds__(256, 2) void k_gemm(const float* __restrict__ bias) {
    extern __shared__ __half sm16[];
    float* cs = (float*)(sm16 + 4 * TILE16);
    float* cq = cs + 128;

    int tid = threadIdx.x;
    int wid = tid >> 5, lane = tid & 31;
    int g = lane >> 2, t = lane & 3;
    int warpM = wid >> 2, warpN = wid & 3;
    int m0 = blockIdx.x * 128;

    if (tid < 128) { cs[tid] = 0.f; cq[tid] = 0.f; }

    uint32_t sb = smem_u32(sm16);

    auto issue = [&](int kk, int buf) {
        uint32_t abase = sb + (uint32_t)(buf * TILE16) * 2u;
#pragma unroll
        for (int i = 0; i < 2; i++) {
            int slot = tid + i * 256;           // 512 slots
            int row = slot >> 2, seg = slot & 3;
            int gm = m0 + row;
            const __half* gp = (kk < 4)
                ? (g_h16 + (size_t)gm * DD + kk * 32 + seg * 8)
                : (g_neigh16 + (size_t)gm * DD + (kk - 4) * 32 + seg * 8);
            cp16(abase + row * (STRD16 * 2) + seg * 16, gp, gm < NN);
        }
        uint32_t bbase = sb + (uint32_t)((2 + buf) * TILE16) * 2u;
#pragma unroll
        for (int i = 0; i < 2; i++) {
            int slot = tid + i * 256;
            int row = slot >> 2, seg = slot & 3;
            cp16(bbase + row * (STRD16 * 2) + seg * 16,
                 g_Wt16 + (size_t)row * 256 + kk * 32 + seg * 8, true);
        }
        CP_COMMIT();
    };

    issue(0, 0);

    float acc[4][4][4];
#pragma unroll
    for (int a = 0; a < 4; a++)
#pragma unroll
        for (int b = 0; b < 4; b++)
#pragma unroll
            for (int c = 0; c < 4; c++) acc[a][b][c] = 0.f;

    CP_WAIT0();
    __syncthreads();

    for (int kk = 0; kk < 8; kk++) {
        int buf = kk & 1;
        if (kk < 7) issue(kk + 1, buf ^ 1);
        const __half* A = sm16 + buf * TILE16;
        const __half* B = sm16 + (2 + buf) * TILE16;
#pragma unroll
        for (int ks = 0; ks < 2; ks++) {
            int kb = ks * 16;
            uint32_t bf[4][2];
#pragma unroll
            for (int nf = 0; nf < 4; nf++) {
                int n = warpN * 32 + nf * 8 + g;
                bf[nf][0] = *(const uint32_t*)&B[n * STRD16 + kb + 2 * t];
                bf[nf][1] = *(const uint32_t*)&B[n * STRD16 + kb + 2 * t + 8];
            }
#pragma unroll
            for (int mf = 0; mf < 4; mf++) {
                int m = warpM * 64 + mf * 16;
                uint32_t a0 = *(const uint32_t*)&A[(m + g) * STRD16 + kb + 2 * t];
                uint32_t a1 = *(const uint32_t*)&A[(m + g + 8) * STRD16 + kb + 2 * t];
                uint32_t a2 = *(const uint32_t*)&A[(m + g) * STRD16 + kb + 2 * t + 8];
                uint32_t a3 = *(const uint32_t*)&A[(m + g + 8) * STRD16 + kb + 2 * t + 8];
#pragma unroll
                for (int nf = 0; nf < 4; nf++)
                    mma16(acc[mf][nf], a0, a1, a2, a3, bf[nf][0], bf[nf][1]);
            }
        }
        CP_WAIT0();
        __syncthreads();
    }

    // ---- epilogue: bias + relu, fp16 store, per-block BN partials (fp32 exact) ----
#pragma unroll
    for (int nf = 0; nf < 4; nf++) {
        int col = warpN * 32 + nf * 8 + 2 * t;
        float2 bv = *(const float2*)(bias + col);
        float s0 = 0.f, s1 = 0.f, q0 = 0.f, q1 = 0.f;
#pragma unroll
        for (int mf = 0; mf < 4; mf++) {
#pragma unroll
            for (int hh = 0; hh < 2; hh++) {
                int row = m0 + warpM * 64 + mf * 16 + g + hh * 8;
                float v0 = fmaxf(acc[mf][nf][hh * 2 + 0] + bv.x, 0.f);
                float v1 = fmaxf(acc[mf][nf][hh * 2 + 1] + bv.y, 0.f);
                if (row < NN) {
                    __half2 p = __float22half2_rn(make_float2(v0, v1));
                    *(__half2*)(g_rst16 + (size_t)row * DD + col) = p;
                    s0 += v0; q0 += v0 * v0;
                    s1 += v1; q1 += v1 * v1;
                }
            }
        }
        atomicAdd(&cs[col], s0);     atomicAdd(&cs[col + 1], s1);
        atomicAdd(&cq[col], q0);     atomicAdd(&cq[col + 1], q1);
    }
    __syncthreads();
    if (tid < 128) {
        atomicAdd(&g_colsum[tid], cs[tid]);
        atomicAdd(&g_colsumsq[tid], cq[tid]);
    }
}

// ---------------------------------------------------------------- fold BN params
__global__ void k_stats(const float* __restrict__ gamma, const float* __restrict__ beta) {
    int j = threadIdx.x;
    if (j >= DD) return;
    float mean = g_colsum[j] / (float)NN;
    float var = g_colsumsq[j] / (float)NN - mean * mean;
    float rs = rsqrtf(var + BN_EPS);
    float sc = rs * gamma[j];
    g_scale[j] = sc;
    g_shift[j] = beta[j] - mean * sc;
}

// ---------------------------------------------------------------- normalize + residual
__global__ void k_final(const float* __restrict__ h, float* __restrict__ out) {
    int i4 = blockIdx.x * blockDim.x + threadIdx.x;
    const int TOT = NN * DD / 4;
    if (i4 >= TOT) return;
    int c4 = i4 & 31;
    uint2 u = ((const uint2*)g_rst16)[i4];
    float2 r0 = __half22float2(*(__half2*)&u.x);
    float2 r1 = __half22float2(*(__half2*)&u.y);
    float4 hv = ((const float4*)h)[i4];
    float4 sc = ((const float4*)g_scale)[c4];
    float4 sh = ((const float4*)g_shift)[c4];
    float4 o;
    o.x = hv.x + r0.x * sc.x + sh.x;
    o.y = hv.y + r0.y * sc.y + sh.y;
    o.z = hv.z + r1.x * sc.z + sh.z;
    o.w = hv.w + r1.y * sc.w + sh.w;
    ((float4*)out)[i4] = o;
}

// ---------------------------------------------------------------- launch
extern "C" void kernel_launch(void* const* d_in, const int* in_sizes, int n_in,
                              void* d_out, int out_size) {
    const float* h     = (const float*)d_in[0];
    const int*   src   = (const int*)d_in[1];
    const int*   dst   = (const int*)d_in[2];
    const float* Ws    = (const float*)d_in[3];
    const float* Wn    = (const float*)d_in[4];
    const float* bias  = (const float*)d_in[5];
    const float* gamma = (const float*)d_in[6];
    const float* beta  = (const float*)d_in[7];
    float* out = (float*)d_out;

    const int GEMM_SMEM = 4 * TILE16 * 2 + 256 * 4;   // 40960 + 1024
    static bool attr_set = false;
    if (!attr_set) {
        cudaFuncSetAttribute(k_gemm, cudaFuncAttributeMaxDynamicSharedMemorySize, GEMM_SMEM);
        attr_set = true;
    }

    k_zero<<<(NN + 255) / 256, 256>>>();
    k_h16<<<(NN * DD / 8 + 255) / 256, 256>>>(h);
    k_wt<<<(128 * 256 + 255) / 256, 256>>>(Ws, Wn);
    k_hist<<<(EE / 4 + 255) / 256, 256>>>(dst);
    k_scan_blk<<<NBLK, 1024>>>();
    k_scan_top<<<1, 128>>>();
    k_scan_add<<<NBLK, 1024>>>();
    k_scatter<<<(EE / 4 + 255) / 256, 256>>>(src, dst);
    k_aggregate<<<(NN * 32 + 255) / 256, 256>>>();
    k_gemm<<<(NN + 127) / 128, 256, GEMM_SMEM>>>(bias);
    k_stats<<<1, 128>>>(gamma, beta);
    k_final<<<(NN * DD / 4 + 255) / 256, 256>>>(h, out);
}